// round 11
// baseline (speedup 1.0000x reference)
#include <cuda_runtime.h>
#include <cuda_fp16.h>
#include <cstdint>

#define EPS_BN 1e-5f
#define NB 16
#define NN 2048
#define NC 128
#define NL 4
#define MTOT (NB * NN)  // 32768

// Scratch (static device globals)
__device__ __half g_adj16[(size_t)NB * NN * NN];   // adj as fp16
__device__ __half g_thi[(size_t)NB * NC * NN];     // t transposed [b][c][n], fp16
__device__ __half g_whi[(size_t)NL * NC * NC];     // W transposed [l][c][k], fp16 hi
__device__ __half g_wlo[(size_t)NL * NC * NC];     // fp16 lo
__device__ float g_h[(size_t)MTOT * NC];
__device__ float g_sum[NC];
__device__ float g_sumsq[NC];
__device__ float g_scale[NC];
__device__ float g_shift[NC];
__device__ int g_cnt;

// ---------------- helpers ----------------
__device__ __forceinline__ uint32_t smem_u32(const void* p) {
    uint32_t a;
    asm("{ .reg .u64 t; cvta.to.shared.u64 t, %1; cvt.u32.u64 %0, t; }" : "=r"(a) : "l"(p));
    return a;
}
__device__ __forceinline__ void ldmx4(uint32_t& r0, uint32_t& r1, uint32_t& r2, uint32_t& r3,
                                      uint32_t addr) {
    asm volatile("ldmatrix.sync.aligned.m8n8.x4.shared.b16 {%0,%1,%2,%3}, [%4];"
                 : "=r"(r0), "=r"(r1), "=r"(r2), "=r"(r3) : "r"(addr));
}
__device__ __forceinline__ void mma_f16(float* d, const uint32_t* a, const uint32_t* b) {
    asm volatile(
        "mma.sync.aligned.m16n8k16.row.col.f32.f16.f16.f32 "
        "{%0,%1,%2,%3}, {%4,%5,%6,%7}, {%8,%9}, {%0,%1,%2,%3};"
        : "+f"(d[0]), "+f"(d[1]), "+f"(d[2]), "+f"(d[3])
        : "r"(a[0]), "r"(a[1]), "r"(a[2]), "r"(a[3]), "r"(b[0]), "r"(b[1]));
}
#define CP16(dst, src) \
    asm volatile("cp.async.cg.shared.global [%0], [%1], 16;" :: "r"(dst), "l"(src))
#define CP_COMMIT() asm volatile("cp.async.commit_group;" ::: "memory")
#define CP_WAIT(n)  asm volatile("cp.async.wait_group %0;" :: "n"(n) : "memory")

__device__ __forceinline__ void split_f16(float v, __half& hi, __half& lo) {
    hi = __float2half_rn(v);
    lo = __float2half_rn(v - __half2float(hi));
}

// ---------------- prep kernels ----------------
__global__ __launch_bounds__(256) void prep_adj(const float* __restrict__ adj) {
    size_t i = (size_t)blockIdx.x * 256 + threadIdx.x;   // float4 index
    float4 v = ((const float4*)adj)[i];
    __half2 a = __floats2half2_rn(v.x, v.y);
    __half2 b = __floats2half2_rn(v.z, v.w);
    uint2 o;
    o.x = *reinterpret_cast<uint32_t*>(&a);
    o.y = *reinterpret_cast<uint32_t*>(&b);
    ((uint2*)g_adj16)[i] = o;
}

__global__ __launch_bounds__(256) void prep_w(const float* __restrict__ W) {
    int id = blockIdx.x * 256 + threadIdx.x;   // 4*128*128 = 65536
    int l = id >> 14, rem = id & 16383;
    int c = rem >> 7, k = rem & 127;
    float v = W[(l << 14) + k * NC + c];
    __half hi, lo;
    split_f16(v, hi, lo);
    g_whi[(l << 14) + c * NC + k] = hi;
    g_wlo[(l << 14) + c * NC + k] = lo;
}

__global__ void zero_stats_kernel() {
    int c = threadIdx.x;
    g_sum[c] = 0.f;
    g_sumsq[c] = 0.f;
    g_scale[c] = 1.f;   // identity affine for layer 0
    g_shift[c] = 0.f;
    if (c == 0) g_cnt = 0;
}

__global__ __launch_bounds__(256) void finalize_kernel(float* __restrict__ out) {
    size_t idx = (size_t)blockIdx.x * blockDim.x + threadIdx.x;
    float4 v = ((const float4*)g_h)[idx];
    int c = (int)((idx & 31) * 4);
    v.x = v.x * g_scale[c + 0] + g_shift[c + 0];
    v.y = v.y * g_scale[c + 1] + g_shift[c + 1];
    v.z = v.z * g_scale[c + 2] + g_shift[c + 2];
    v.w = v.w * g_scale[c + 3] + g_shift[c + 3];
    ((float4*)out)[idx] = v;
}

// ---------------- gemm_hw_mma: t_T[c][n] = sum_k W'[c][k] * affine(h)[n][k] ----------------
// 3-pass hi/lo, K=128 fully resident, 8 warps 2M(c) x 4N(n), warp tile 64x32
constexpr int P2 = 272;               // 256B data + 16B pad
constexpr int WB = 128 * P2;          // 34816
constexpr int OFF_HHI = 2 * WB;
constexpr int OFF_HLO = 3 * WB;
constexpr int SMEM_HW = 4 * WB + 256; // 139520

__global__ void __launch_bounds__(256, 1)
gemm_hw_mma(const float* __restrict__ hin, int layer) {
    extern __shared__ __align__(128) char smem[];
    const int tid = threadIdx.x;
    const int wid = tid >> 5, lane = tid & 31;
    const int warpM = wid >> 2, warpN = wid & 3;   // 2M x 4N
    const int batch = blockIdx.y;
    const int n0 = blockIdx.x * 128;
    const uint32_t sb = smem_u32(smem);

    // A: W' hi/lo via cp.async (k-contiguous rows of 256B)
    const char* Wh = (const char*)(g_whi + ((size_t)layer << 14));
    const char* Wl = (const char*)(g_wlo + ((size_t)layer << 14));
    #pragma unroll
    for (int q = 0; q < 8; q++) {
        int id = tid + 256 * q;
        int r = id >> 4, j = id & 15;
        CP16(sb + r * P2 + j * 16, Wh + r * 256 + j * 16);
        CP16(sb + WB + r * P2 + j * 16, Wl + r * 256 + j * 16);
    }
    CP_COMMIT();

    // B: affine(h) converted + split in-registers -> smem
    const float* hb = (hin ? hin : g_h) + ((size_t)batch * NN + n0) * NC;
    #pragma unroll
    for (int q = 0; q < 16; q++) {
        int id = tid + 256 * q;
        int r = id >> 5, g = id & 31;          // r: n-row, g: float4 within 128 k
        float4 v = *(const float4*)(hb + (size_t)r * NC + g * 4);
        int k0 = g * 4;
        v.x = v.x * g_scale[k0 + 0] + g_shift[k0 + 0];
        v.y = v.y * g_scale[k0 + 1] + g_shift[k0 + 1];
        v.z = v.z * g_scale[k0 + 2] + g_shift[k0 + 2];
        v.w = v.w * g_scale[k0 + 3] + g_shift[k0 + 3];
        __half h0, h1, h2, h3, l0, l1, l2, l3;
        split_f16(v.x, h0, l0);
        split_f16(v.y, h1, l1);
        split_f16(v.z, h2, l2);
        split_f16(v.w, h3, l3);
        __half hh[4] = {h0, h1, h2, h3};
        __half ll[4] = {l0, l1, l2, l3};
        *(uint2*)(smem + OFF_HHI + r * P2 + g * 8) = *(uint2*)hh;
        *(uint2*)(smem + OFF_HLO + r * P2 + g * 8) = *(uint2*)ll;
    }
    CP_WAIT(0);
    __syncthreads();

    float acc[4][4][4] = {};
    const uint32_t a_off = (uint32_t)((warpM * 64 + (lane & 15)) * P2 + ((lane >> 4) << 4));
    const int bg = lane >> 3;
    const uint32_t b_row = (uint32_t)(warpN * 32 + (bg >> 1) * 8 + (lane & 7));
    const uint32_t b_off = b_row * P2 + (uint32_t)((bg & 1) << 4);

    #pragma unroll
    for (int ks = 0; ks < 8; ks++) {
        const uint32_t kb = (uint32_t)(ks * 32);
        uint32_t bh[8], bl[8];
        ldmx4(bh[0], bh[1], bh[2], bh[3], sb + OFF_HHI + b_off + kb);
        ldmx4(bh[4], bh[5], bh[6], bh[7], sb + OFF_HHI + b_off + kb + 16 * P2);
        ldmx4(bl[0], bl[1], bl[2], bl[3], sb + OFF_HLO + b_off + kb);
        ldmx4(bl[4], bl[5], bl[6], bl[7], sb + OFF_HLO + b_off + kb + 16 * P2);
        #pragma unroll
        for (int mi = 0; mi < 4; mi++) {
            uint32_t ah[4], al[4];
            uint32_t ao = a_off + (uint32_t)(mi * 16 * P2) + kb;
            ldmx4(ah[0], ah[1], ah[2], ah[3], sb + ao);
            ldmx4(al[0], al[1], al[2], al[3], sb + WB + ao);
            #pragma unroll
            for (int ni = 0; ni < 4; ni++) {
                mma_f16(acc[mi][ni], ah, &bh[ni * 2]);
                mma_f16(acc[mi][ni], ah, &bl[ni * 2]);
                mma_f16(acc[mi][ni], al, &bh[ni * 2]);
            }
        }
    }

    // epilogue: write t as fp16 [b][c][n]
    __half* Tb = g_thi + (size_t)batch * NC * NN;
    #pragma unroll
    for (int mi = 0; mi < 4; mi++) {
        #pragma unroll
        for (int hf = 0; hf < 2; hf++) {
            int c = warpM * 64 + mi * 16 + (lane >> 2) + hf * 8;
            #pragma unroll
            for (int ni = 0; ni < 4; ni++) {
                int n = n0 + warpN * 32 + (lane & 3) * 2 + ni * 8;
                __half2 hv = __floats2half2_rn(acc[mi][ni][hf * 2 + 0],
                                               acc[mi][ni][hf * 2 + 1]);
                *(__half2*)(Tb + (size_t)c * NN + n) = hv;
            }
        }
    }
}

// ---------------- gemm_adj: fp16 mma.sync, 128x128 CTA, 3-stage (R8-proven) ----------------
constexpr int PITCH = 144;
constexpr int ABUF = 128 * PITCH;     // 18432 B
constexpr int STG = 2 * ABUF;         // 36864
constexpr int NSTG = 3;
constexpr int OFF_SUM = NSTG * STG;   // 110592
constexpr int SMEM_SZ = OFF_SUM + 1024;
constexpr int NKT = NN / 64;          // 32 k-tiles

__device__ __forceinline__ void prefetch(uint32_t sbase, int st,
                                         const char* Ab, const char* Hb,
                                         int kt, int tid) {
    uint32_t d = sbase + st * STG;
    const int koff = kt * 128;
    #pragma unroll
    for (int q = 0; q < 4; q++) {
        int id = tid + 256 * q;
        int r = id >> 3, j = id & 7;
        CP16(d + r * PITCH + j * 16, Ab + (size_t)r * (NN * 2) + koff + j * 16);
    }
    #pragma unroll
    for (int q = 0; q < 4; q++) {
        int id = tid + 256 * q;
        int c = id >> 3, j = id & 7;
        CP16(d + ABUF + c * PITCH + j * 16, Hb + (size_t)c * (NN * 2) + koff + j * 16);
    }
    CP_COMMIT();
}

__global__ void __launch_bounds__(256, 2)
gemm_adj_mma(const float* __restrict__ bias, const float* __restrict__ gamma,
             const float* __restrict__ beta) {
    extern __shared__ __align__(128) char smem[];
    const int tid = threadIdx.x;
    const int wid = tid >> 5, lane = tid & 31;
    const int warpM = wid >> 2, warpN = wid & 3;
    const int batch = blockIdx.y;
    const int row0 = blockIdx.x * 128;
    const uint32_t sb = smem_u32(smem);
    float* s_sum = (float*)(smem + OFF_SUM);
    float* s_sq = (float*)(smem + OFF_SUM + 512);
    __shared__ int s_last;

    if (tid < 128) { s_sum[tid] = 0.f; s_sq[tid] = 0.f; }

    const char* Ab = (const char*)(g_adj16 + (size_t)batch * NN * NN + (size_t)row0 * NN);
    const char* Hb = (const char*)(g_thi + (size_t)batch * NC * NN);

    float acc[4][4][4] = {};

    const uint32_t a_off = (uint32_t)((warpM * 64 + (lane & 15)) * PITCH + ((lane >> 4) << 4));
    const int bg = lane >> 3;
    const uint32_t b_row = (uint32_t)(warpN * 32 + (bg >> 1) * 8 + (lane & 7));
    const uint32_t b_off = b_row * PITCH + (uint32_t)((bg & 1) << 4);

    prefetch(sb, 0, Ab, Hb, 0, tid);
    prefetch(sb, 1, Ab, Hb, 1, tid);

    int st = 0;
    for (int kt = 0; kt < NKT; kt++) {
        if (kt < NKT - 1) CP_WAIT(1);
        else CP_WAIT(0);
        __syncthreads();

        if (kt + 2 < NKT)
            prefetch(sb, (st + 2 >= NSTG) ? st + 2 - NSTG : st + 2, Ab, Hb, kt + 2, tid);

        const uint32_t sA = sb + st * STG;
        const uint32_t sB = sA + ABUF;

        #pragma unroll
        for (int ks = 0; ks < 4; ks++) {
            const uint32_t kb = (uint32_t)(ks * 32);
            uint32_t bh[8];
            ldmx4(bh[0], bh[1], bh[2], bh[3], sB + b_off + kb);
            ldmx4(bh[4], bh[5], bh[6], bh[7], sB + b_off + kb + 16 * PITCH);
            #pragma unroll
            for (int mi = 0; mi < 4; mi++) {
                uint32_t a[4];
                ldmx4(a[0], a[1], a[2], a[3], sA + a_off + (uint32_t)(mi * 16 * PITCH) + kb);
                #pragma unroll
                for (int ni = 0; ni < 4; ni++)
                    mma_f16(acc[mi][ni], a, &bh[ni * 2]);
            }
        }
        st = (st + 1 == NSTG) ? 0 : st + 1;
    }

    // epilogue: bias + relu + store + stats
    float2 bv[4];
    const int cbase = warpN * 32 + (lane & 3) * 2;
    #pragma unroll
    for (int ni = 0; ni < 4; ni++)
        bv[ni] = *(const float2*)(bias + cbase + ni * 8);

    float ts[4][2] = {}, tq[4][2] = {};
    float* Yb = g_h + ((size_t)batch * NN + row0) * NC;
    #pragma unroll
    for (int mi = 0; mi < 4; mi++) {
        #pragma unroll
        for (int hf = 0; hf < 2; hf++) {
            int row = warpM * 64 + mi * 16 + (lane >> 2) + hf * 8;
            float* rp = Yb + (size_t)row * NC + cbase;
            #pragma unroll
            for (int ni = 0; ni < 4; ni++) {
                float v0 = fmaxf(acc[mi][ni][hf * 2 + 0] + bv[ni].x, 0.f);
                float v1 = fmaxf(acc[mi][ni][hf * 2 + 1] + bv[ni].y, 0.f);
                *(float2*)(rp + ni * 8) = make_float2(v0, v1);
                ts[ni][0] += v0;
                ts[ni][1] += v1;
                tq[ni][0] = fmaf(v0, v0, tq[ni][0]);
                tq[ni][1] = fmaf(v1, v1, tq[ni][1]);
            }
        }
    }
    #pragma unroll
    for (int ni = 0; ni < 4; ni++) {
        atomicAdd(&s_sum[cbase + ni * 8], ts[ni][0]);
        atomicAdd(&s_sum[cbase + ni * 8 + 1], ts[ni][1]);
        atomicAdd(&s_sq[cbase + ni * 8], tq[ni][0]);
        atomicAdd(&s_sq[cbase + ni * 8 + 1], tq[ni][1]);
    }
    __syncthreads();
    if (tid < 128) {
        atomicAdd(&g_sum[tid], s_sum[tid]);
        atomicAdd(&g_sumsq[tid], s_sq[tid]);
    }

    // fused bn_stats
    __threadfence();
    if (tid == 0)
        s_last = (atomicAdd(&g_cnt, 1) == NB * (NN / 128) - 1) ? 1 : 0;
    __syncthreads();
    if (s_last) {
        if (tid == 0) g_cnt = 0;
        if (tid < NC) {
            const float inv = 1.0f / (float)MTOT;
            float mean = g_sum[tid] * inv;
            float var = g_sumsq[tid] * inv - mean * mean;
            float sc = gamma[tid] * rsqrtf(var + EPS_BN);
            g_scale[tid] = sc;
            g_shift[tid] = beta[tid] - mean * sc;
            g_sum[tid] = 0.f;
            g_sumsq[tid] = 0.f;
        }
    }
}

// ---------------- host ----------------
extern "C" void kernel_launch(void* const* d_in, const int* in_sizes, int n_in,
                              void* d_out, int out_size) {
    const float* x     = (const float*)d_in[0];
    const float* adj   = (const float*)d_in[1];
    const float* W     = (const float*)d_in[2];
    const float* bias  = (const float*)d_in[3];
    const float* gamma = (const float*)d_in[4];
    const float* beta  = (const float*)d_in[5];
    float* out = (float*)d_out;

    cudaFuncSetAttribute(gemm_adj_mma, cudaFuncAttributeMaxDynamicSharedMemorySize, SMEM_SZ);
    cudaFuncSetAttribute(gemm_hw_mma, cudaFuncAttributeMaxDynamicSharedMemorySize, SMEM_HW);

    prep_adj<<<(int)(((size_t)NB * NN * NN / 4) / 256), 256>>>(adj);
    prep_w<<<(NL * NC * NC) / 256, 256>>>(W);
    zero_stats_kernel<<<1, NC>>>();

    for (int l = 0; l < NL; l++) {
        gemm_hw_mma<<<dim3(NN / 128, NB), 256, SMEM_HW>>>(l == 0 ? x : nullptr, l);
        gemm_adj_mma<<<dim3(NN / 128, NB), 256, SMEM_SZ>>>(bias + (size_t)l * NC,
                                                           gamma + (size_t)l * NC,
                                                           beta + (size_t)l * NC);
    }
    finalize_kernel<<<(MTOT * NC / 4) / 256, 256>>>(out);
}

// round 12
// speedup vs baseline: 1.0095x; 1.0095x over previous
#include <cuda_runtime.h>
#include <cuda_fp16.h>
#include <cstdint>

#define EPS_BN 1e-5f
#define NB 16
#define NN 2048
#define NC 128
#define NL 4
#define MTOT (NB * NN)  // 32768

// Scratch (static device globals)
__device__ __half g_adj16[(size_t)NB * NN * NN];   // adj as fp16
__device__ __half g_thi[(size_t)NB * NC * NN];     // t transposed [b][c][n], fp16
__device__ __half g_whi[(size_t)NL * NC * NC];     // W transposed [l][c][k], fp16 hi
__device__ __half g_wlo[(size_t)NL * NC * NC];     // fp16 lo
__device__ float g_h[(size_t)MTOT * NC];
__device__ float g_sum[NC];
__device__ float g_sumsq[NC];
__device__ float g_scale[NC];
__device__ float g_shift[NC];
__device__ int g_cnt;

// ---------------- helpers ----------------
__device__ __forceinline__ uint32_t smem_u32(const void* p) {
    uint32_t a;
    asm("{ .reg .u64 t; cvta.to.shared.u64 t, %1; cvt.u32.u64 %0, t; }" : "=r"(a) : "l"(p));
    return a;
}
__device__ __forceinline__ void ldmx4(uint32_t& r0, uint32_t& r1, uint32_t& r2, uint32_t& r3,
                                      uint32_t addr) {
    asm volatile("ldmatrix.sync.aligned.m8n8.x4.shared.b16 {%0,%1,%2,%3}, [%4];"
                 : "=r"(r0), "=r"(r1), "=r"(r2), "=r"(r3) : "r"(addr));
}
__device__ __forceinline__ void mma_f16(float* d, const uint32_t* a, const uint32_t* b) {
    asm volatile(
        "mma.sync.aligned.m16n8k16.row.col.f32.f16.f16.f32 "
        "{%0,%1,%2,%3}, {%4,%5,%6,%7}, {%8,%9}, {%0,%1,%2,%3};"
        : "+f"(d[0]), "+f"(d[1]), "+f"(d[2]), "+f"(d[3])
        : "r"(a[0]), "r"(a[1]), "r"(a[2]), "r"(a[3]), "r"(b[0]), "r"(b[1]));
}
#define CP16(dst, src) \
    asm volatile("cp.async.cg.shared.global [%0], [%1], 16;" :: "r"(dst), "l"(src))
#define CP_COMMIT() asm volatile("cp.async.commit_group;" ::: "memory")
#define CP_WAIT(n)  asm volatile("cp.async.wait_group %0;" :: "n"(n) : "memory")

__device__ __forceinline__ void split_f16(float v, __half& hi, __half& lo) {
    hi = __float2half_rn(v);
    lo = __float2half_rn(v - __half2float(hi));
}

// ---------------- prep kernels ----------------
__global__ __launch_bounds__(256) void prep_adj(const float* __restrict__ adj) {
    size_t i = (size_t)blockIdx.x * 256 + threadIdx.x;   // float4 index
    float4 v = ((const float4*)adj)[i];
    __half2 a = __floats2half2_rn(v.x, v.y);
    __half2 b = __floats2half2_rn(v.z, v.w);
    uint2 o;
    o.x = *reinterpret_cast<uint32_t*>(&a);
    o.y = *reinterpret_cast<uint32_t*>(&b);
    ((uint2*)g_adj16)[i] = o;
}

__global__ __launch_bounds__(256) void prep_w(const float* __restrict__ W) {
    int id = blockIdx.x * 256 + threadIdx.x;   // 4*128*128 = 65536
    int l = id >> 14, rem = id & 16383;
    int c = rem >> 7, k = rem & 127;
    float v = W[(l << 14) + k * NC + c];
    __half hi, lo;
    split_f16(v, hi, lo);
    g_whi[(l << 14) + c * NC + k] = hi;
    g_wlo[(l << 14) + c * NC + k] = lo;
}

__global__ void zero_stats_kernel() {
    int c = threadIdx.x;
    g_sum[c] = 0.f;
    g_sumsq[c] = 0.f;
    g_scale[c] = 1.f;   // identity affine for layer 0
    g_shift[c] = 0.f;
    if (c == 0) g_cnt = 0;
}

__global__ __launch_bounds__(256) void finalize_kernel(float* __restrict__ out) {
    size_t idx = (size_t)blockIdx.x * blockDim.x + threadIdx.x;
    float4 v = ((const float4*)g_h)[idx];
    int c = (int)((idx & 31) * 4);
    v.x = v.x * g_scale[c + 0] + g_shift[c + 0];
    v.y = v.y * g_scale[c + 1] + g_shift[c + 1];
    v.z = v.z * g_scale[c + 2] + g_shift[c + 2];
    v.w = v.w * g_scale[c + 3] + g_shift[c + 3];
    ((float4*)out)[idx] = v;
}

// ---------------- gemm_hw_mma: t_T[c][n] = sum_k W'[c][k] * affine(h)[n][k] ----------------
// 3-pass hi/lo, K=128 resident, B tile 64 n-rows, 8 warps 4M(c) x 2N(n), warp 32x32
constexpr int P2 = 272;               // 256B data + 16B pad
constexpr int WB = 128 * P2;          // 34816 (W: 128 c-rows)
constexpr int HB2 = 64 * P2;          // 17408 (h: 64 n-rows)
constexpr int OFF_HHI = 2 * WB;       // 69632
constexpr int OFF_HLO = 2 * WB + HB2; // 87040
constexpr int SMEM_HW = 2 * WB + 2 * HB2 + 256;  // 104704

__global__ void __launch_bounds__(256, 2)
gemm_hw_mma(const float* __restrict__ hin, int layer) {
    extern __shared__ __align__(128) char smem[];
    const int tid = threadIdx.x;
    const int wid = tid >> 5, lane = tid & 31;
    const int warpM = wid >> 1, warpN = wid & 1;   // 4M x 2N, warp tile 32x32
    const int batch = blockIdx.y;
    const int n0 = blockIdx.x * 64;
    const uint32_t sb = smem_u32(smem);

    // A: W' hi/lo via cp.async (k-contiguous rows of 256B)
    const char* Wh = (const char*)(g_whi + ((size_t)layer << 14));
    const char* Wl = (const char*)(g_wlo + ((size_t)layer << 14));
    #pragma unroll
    for (int q = 0; q < 8; q++) {
        int id = tid + 256 * q;
        int r = id >> 4, j = id & 15;
        CP16(sb + r * P2 + j * 16, Wh + r * 256 + j * 16);
        CP16(sb + WB + r * P2 + j * 16, Wl + r * 256 + j * 16);
    }
    CP_COMMIT();

    // B: affine(h) converted + split in-registers -> smem (64 rows x 128 k)
    const float* hb = (hin ? hin : g_h) + ((size_t)batch * NN + n0) * NC;
    #pragma unroll
    for (int q = 0; q < 8; q++) {
        int id = tid + 256 * q;
        int r = id >> 5, g = id & 31;          // r: n-row (0-63), g: float4 within 128 k
        float4 v = *(const float4*)(hb + (size_t)r * NC + g * 4);
        int k0 = g * 4;
        v.x = v.x * g_scale[k0 + 0] + g_shift[k0 + 0];
        v.y = v.y * g_scale[k0 + 1] + g_shift[k0 + 1];
        v.z = v.z * g_scale[k0 + 2] + g_shift[k0 + 2];
        v.w = v.w * g_scale[k0 + 3] + g_shift[k0 + 3];
        __half h0, h1, h2, h3, l0, l1, l2, l3;
        split_f16(v.x, h0, l0);
        split_f16(v.y, h1, l1);
        split_f16(v.z, h2, l2);
        split_f16(v.w, h3, l3);
        __half hh[4] = {h0, h1, h2, h3};
        __half ll[4] = {l0, l1, l2, l3};
        *(uint2*)(smem + OFF_HHI + r * P2 + g * 8) = *(uint2*)hh;
        *(uint2*)(smem + OFF_HLO + r * P2 + g * 8) = *(uint2*)ll;
    }
    CP_WAIT(0);
    __syncthreads();

    float acc[2][4][4] = {};
    const uint32_t a_off = (uint32_t)((warpM * 32 + (lane & 15)) * P2 + ((lane >> 4) << 4));
    const int bg = lane >> 3;
    const uint32_t b_row = (uint32_t)(warpN * 32 + (bg >> 1) * 8 + (lane & 7));
    const uint32_t b_off = b_row * P2 + (uint32_t)((bg & 1) << 4);

    #pragma unroll
    for (int ks = 0; ks < 8; ks++) {
        const uint32_t kb = (uint32_t)(ks * 32);
        uint32_t bh[8], bl[8];
        ldmx4(bh[0], bh[1], bh[2], bh[3], sb + OFF_HHI + b_off + kb);
        ldmx4(bh[4], bh[5], bh[6], bh[7], sb + OFF_HHI + b_off + kb + 16 * P2);
        ldmx4(bl[0], bl[1], bl[2], bl[3], sb + OFF_HLO + b_off + kb);
        ldmx4(bl[4], bl[5], bl[6], bl[7], sb + OFF_HLO + b_off + kb + 16 * P2);
        #pragma unroll
        for (int mi = 0; mi < 2; mi++) {
            uint32_t ah[4], al[4];
            uint32_t ao = a_off + (uint32_t)(mi * 16 * P2) + kb;
            ldmx4(ah[0], ah[1], ah[2], ah[3], sb + ao);
            ldmx4(al[0], al[1], al[2], al[3], sb + WB + ao);
            #pragma unroll
            for (int ni = 0; ni < 4; ni++) {
                mma_f16(acc[mi][ni], ah, &bh[ni * 2]);
                mma_f16(acc[mi][ni], ah, &bl[ni * 2]);
                mma_f16(acc[mi][ni], al, &bh[ni * 2]);
            }
        }
    }

    // epilogue: write t as fp16 [b][c][n]
    __half* Tb = g_thi + (size_t)batch * NC * NN;
    #pragma unroll
    for (int mi = 0; mi < 2; mi++) {
        #pragma unroll
        for (int hf = 0; hf < 2; hf++) {
            int c = warpM * 32 + mi * 16 + (lane >> 2) + hf * 8;
            #pragma unroll
            for (int ni = 0; ni < 4; ni++) {
                int n = n0 + warpN * 32 + (lane & 3) * 2 + ni * 8;
                __half2 hv = __floats2half2_rn(acc[mi][ni][hf * 2 + 0],
                                               acc[mi][ni][hf * 2 + 1]);
                *(__half2*)(Tb + (size_t)c * NN + n) = hv;
            }
        }
    }
}

// ---------------- gemm_adj: fp16 mma.sync, 128x128 CTA, 3-stage (R8-proven) ----------------
constexpr int PITCH = 144;
constexpr int ABUF = 128 * PITCH;     // 18432 B
constexpr int STG = 2 * ABUF;         // 36864
constexpr int NSTG = 3;
constexpr int OFF_SUM = NSTG * STG;   // 110592
constexpr int SMEM_SZ = OFF_SUM + 1024;
constexpr int NKT = NN / 64;          // 32 k-tiles

__device__ __forceinline__ void prefetch(uint32_t sbase, int st,
                                         const char* Ab, const char* Hb,
                                         int kt, int tid) {
    uint32_t d = sbase + st * STG;
    const int koff = kt * 128;
    #pragma unroll
    for (int q = 0; q < 4; q++) {
        int id = tid + 256 * q;
        int r = id >> 3, j = id & 7;
        CP16(d + r * PITCH + j * 16, Ab + (size_t)r * (NN * 2) + koff + j * 16);
    }
    #pragma unroll
    for (int q = 0; q < 4; q++) {
        int id = tid + 256 * q;
        int c = id >> 3, j = id & 7;
        CP16(d + ABUF + c * PITCH + j * 16, Hb + (size_t)c * (NN * 2) + koff + j * 16);
    }
    CP_COMMIT();
}

__global__ void __launch_bounds__(256, 2)
gemm_adj_mma(const float* __restrict__ bias, const float* __restrict__ gamma,
             const float* __restrict__ beta) {
    extern __shared__ __align__(128) char smem[];
    const int tid = threadIdx.x;
    const int wid = tid >> 5, lane = tid & 31;
    const int warpM = wid >> 2, warpN = wid & 3;
    const int batch = blockIdx.y;
    const int row0 = blockIdx.x * 128;
    const uint32_t sb = smem_u32(smem);
    float* s_sum = (float*)(smem + OFF_SUM);
    float* s_sq = (float*)(smem + OFF_SUM + 512);
    __shared__ int s_last;

    if (tid < 128) { s_sum[tid] = 0.f; s_sq[tid] = 0.f; }

    const char* Ab = (const char*)(g_adj16 + (size_t)batch * NN * NN + (size_t)row0 * NN);
    const char* Hb = (const char*)(g_thi + (size_t)batch * NC * NN);

    float acc[4][4][4] = {};

    const uint32_t a_off = (uint32_t)((warpM * 64 + (lane & 15)) * PITCH + ((lane >> 4) << 4));
    const int bg = lane >> 3;
    const uint32_t b_row = (uint32_t)(warpN * 32 + (bg >> 1) * 8 + (lane & 7));
    const uint32_t b_off = b_row * PITCH + (uint32_t)((bg & 1) << 4);

    prefetch(sb, 0, Ab, Hb, 0, tid);
    prefetch(sb, 1, Ab, Hb, 1, tid);

    int st = 0;
    for (int kt = 0; kt < NKT; kt++) {
        if (kt < NKT - 1) CP_WAIT(1);
        else CP_WAIT(0);
        __syncthreads();

        if (kt + 2 < NKT)
            prefetch(sb, (st + 2 >= NSTG) ? st + 2 - NSTG : st + 2, Ab, Hb, kt + 2, tid);

        const uint32_t sA = sb + st * STG;
        const uint32_t sB = sA + ABUF;

        #pragma unroll
        for (int ks = 0; ks < 4; ks++) {
            const uint32_t kb = (uint32_t)(ks * 32);
            uint32_t bh[8];
            ldmx4(bh[0], bh[1], bh[2], bh[3], sB + b_off + kb);
            ldmx4(bh[4], bh[5], bh[6], bh[7], sB + b_off + kb + 16 * PITCH);
            #pragma unroll
            for (int mi = 0; mi < 4; mi++) {
                uint32_t a[4];
                ldmx4(a[0], a[1], a[2], a[3], sA + a_off + (uint32_t)(mi * 16 * PITCH) + kb);
                #pragma unroll
                for (int ni = 0; ni < 4; ni++)
                    mma_f16(acc[mi][ni], a, &bh[ni * 2]);
            }
        }
        st = (st + 1 == NSTG) ? 0 : st + 1;
    }

    // epilogue: bias + relu + store + stats
    float2 bv[4];
    const int cbase = warpN * 32 + (lane & 3) * 2;
    #pragma unroll
    for (int ni = 0; ni < 4; ni++)
        bv[ni] = *(const float2*)(bias + cbase + ni * 8);

    float ts[4][2] = {}, tq[4][2] = {};
    float* Yb = g_h + ((size_t)batch * NN + row0) * NC;
    #pragma unroll
    for (int mi = 0; mi < 4; mi++) {
        #pragma unroll
        for (int hf = 0; hf < 2; hf++) {
            int row = warpM * 64 + mi * 16 + (lane >> 2) + hf * 8;
            float* rp = Yb + (size_t)row * NC + cbase;
            #pragma unroll
            for (int ni = 0; ni < 4; ni++) {
                float v0 = fmaxf(acc[mi][ni][hf * 2 + 0] + bv[ni].x, 0.f);
                float v1 = fmaxf(acc[mi][ni][hf * 2 + 1] + bv[ni].y, 0.f);
                *(float2*)(rp + ni * 8) = make_float2(v0, v1);
                ts[ni][0] += v0;
                ts[ni][1] += v1;
                tq[ni][0] = fmaf(v0, v0, tq[ni][0]);
                tq[ni][1] = fmaf(v1, v1, tq[ni][1]);
            }
        }
    }
    #pragma unroll
    for (int ni = 0; ni < 4; ni++) {
        atomicAdd(&s_sum[cbase + ni * 8], ts[ni][0]);
        atomicAdd(&s_sum[cbase + ni * 8 + 1], ts[ni][1]);
        atomicAdd(&s_sq[cbase + ni * 8], tq[ni][0]);
        atomicAdd(&s_sq[cbase + ni * 8 + 1], tq[ni][1]);
    }
    __syncthreads();
    if (tid < 128) {
        atomicAdd(&g_sum[tid], s_sum[tid]);
        atomicAdd(&g_sumsq[tid], s_sq[tid]);
    }

    // fused bn_stats
    __threadfence();
    if (tid == 0)
        s_last = (atomicAdd(&g_cnt, 1) == NB * (NN / 128) - 1) ? 1 : 0;
    __syncthreads();
    if (s_last) {
        if (tid == 0) g_cnt = 0;
        if (tid < NC) {
            const float inv = 1.0f / (float)MTOT;
            float mean = g_sum[tid] * inv;
            float var = g_sumsq[tid] * inv - mean * mean;
            float sc = gamma[tid] * rsqrtf(var + EPS_BN);
            g_scale[tid] = sc;
            g_shift[tid] = beta[tid] - mean * sc;
            g_sum[tid] = 0.f;
            g_sumsq[tid] = 0.f;
        }
    }
}

// ---------------- host ----------------
extern "C" void kernel_launch(void* const* d_in, const int* in_sizes, int n_in,
                              void* d_out, int out_size) {
    const float* x     = (const float*)d_in[0];
    const float* adj   = (const float*)d_in[1];
    const float* W     = (const float*)d_in[2];
    const float* bias  = (const float*)d_in[3];
    const float* gamma = (const float*)d_in[4];
    const float* beta  = (const float*)d_in[5];
    float* out = (float*)d_out;

    cudaFuncSetAttribute(gemm_adj_mma, cudaFuncAttributeMaxDynamicSharedMemorySize, SMEM_SZ);
    cudaFuncSetAttribute(gemm_hw_mma, cudaFuncAttributeMaxDynamicSharedMemorySize, SMEM_HW);

    prep_adj<<<(int)(((size_t)NB * NN * NN / 4) / 256), 256>>>(adj);
    prep_w<<<(NL * NC * NC) / 256, 256>>>(W);
    zero_stats_kernel<<<1, NC>>>();

    for (int l = 0; l < NL; l++) {
        gemm_hw_mma<<<dim3(NN / 64, NB), 256, SMEM_HW>>>(l == 0 ? x : nullptr, l);
        gemm_adj_mma<<<dim3(NN / 128, NB), 256, SMEM_SZ>>>(bias + (size_t)l * NC,
                                                           gamma + (size_t)l * NC,
                                                           beta + (size_t)l * NC);
    }
    finalize_kernel<<<(MTOT * NC / 4) / 256, 256>>>(out);
}

// round 13
// speedup vs baseline: 1.0419x; 1.0321x over previous
#include <cuda_runtime.h>
#include <cuda_fp16.h>
#include <cstdint>

#define EPS_BN 1e-5f
#define NB 16
#define NN 2048
#define NC 128
#define NL 4
#define MTOT (NB * NN)  // 32768

// Scratch (static device globals)
__device__ __half g_adj16[(size_t)NB * NN * NN];   // adj as fp16
__device__ __half g_thi[(size_t)NB * NC * NN];     // t transposed [b][c][n], fp16
__device__ __half g_whi[(size_t)NL * NC * NC];     // W transposed [l][c][k], fp16
__device__ float g_h[(size_t)MTOT * NC];
__device__ float g_sum[NC];
__device__ float g_sumsq[NC];
__device__ float g_scale[NC];
__device__ float g_shift[NC];
__device__ int g_cnt;

// ---------------- helpers ----------------
__device__ __forceinline__ uint32_t smem_u32(const void* p) {
    uint32_t a;
    asm("{ .reg .u64 t; cvta.to.shared.u64 t, %1; cvt.u32.u64 %0, t; }" : "=r"(a) : "l"(p));
    return a;
}
__device__ __forceinline__ void ldmx4(uint32_t& r0, uint32_t& r1, uint32_t& r2, uint32_t& r3,
                                      uint32_t addr) {
    asm volatile("ldmatrix.sync.aligned.m8n8.x4.shared.b16 {%0,%1,%2,%3}, [%4];"
                 : "=r"(r0), "=r"(r1), "=r"(r2), "=r"(r3) : "r"(addr));
}
__device__ __forceinline__ void mma_f16(float* d, const uint32_t* a, const uint32_t* b) {
    asm volatile(
        "mma.sync.aligned.m16n8k16.row.col.f32.f16.f16.f32 "
        "{%0,%1,%2,%3}, {%4,%5,%6,%7}, {%8,%9}, {%0,%1,%2,%3};"
        : "+f"(d[0]), "+f"(d[1]), "+f"(d[2]), "+f"(d[3])
        : "r"(a[0]), "r"(a[1]), "r"(a[2]), "r"(a[3]), "r"(b[0]), "r"(b[1]));
}
#define CP16(dst, src) \
    asm volatile("cp.async.cg.shared.global [%0], [%1], 16;" :: "r"(dst), "l"(src))
#define CP_COMMIT() asm volatile("cp.async.commit_group;" ::: "memory")
#define CP_WAIT(n)  asm volatile("cp.async.wait_group %0;" :: "n"(n) : "memory")

__device__ __forceinline__ void split_f16(float v, __half& hi, __half& lo) {
    hi = __float2half_rn(v);
    lo = __float2half_rn(v - __half2float(hi));
}

// ---------------- prep kernels ----------------
__global__ __launch_bounds__(256) void prep_adj(const float* __restrict__ adj) {
    size_t i = (size_t)blockIdx.x * 256 + threadIdx.x;   // float4 index
    float4 v = ((const float4*)adj)[i];
    __half2 a = __floats2half2_rn(v.x, v.y);
    __half2 b = __floats2half2_rn(v.z, v.w);
    uint2 o;
    o.x = *reinterpret_cast<uint32_t*>(&a);
    o.y = *reinterpret_cast<uint32_t*>(&b);
    ((uint2*)g_adj16)[i] = o;
}

__global__ __launch_bounds__(256) void prep_w(const float* __restrict__ W) {
    int id = blockIdx.x * 256 + threadIdx.x;   // 4*128*128 = 65536
    int l = id >> 14, rem = id & 16383;
    int c = rem >> 7, k = rem & 127;
    g_whi[(l << 14) + c * NC + k] = __float2half_rn(W[(l << 14) + k * NC + c]);
}

__global__ void zero_stats_kernel() {
    int c = threadIdx.x;
    g_sum[c] = 0.f;
    g_sumsq[c] = 0.f;
    g_scale[c] = 1.f;   // identity affine for layer 0
    g_shift[c] = 0.f;
    if (c == 0) g_cnt = 0;
}

__global__ __launch_bounds__(256) void finalize_kernel(float* __restrict__ out) {
    size_t idx = (size_t)blockIdx.x * blockDim.x + threadIdx.x;
    float4 v = ((const float4*)g_h)[idx];
    int c = (int)((idx & 31) * 4);
    v.x = v.x * g_scale[c + 0] + g_shift[c + 0];
    v.y = v.y * g_scale[c + 1] + g_shift[c + 1];
    v.z = v.z * g_scale[c + 2] + g_shift[c + 2];
    v.w = v.w * g_scale[c + 3] + g_shift[c + 3];
    ((float4*)out)[idx] = v;
}

// ---------------- gemm_hw_mma: t_T[c][n] = sum_k W'[c][k] * affine(h)[n][k] ----------------
// 2-pass (Whi * (hhi + hlo)), K=128 resident, B tile 64 n-rows, 8 warps 4Mx2N
constexpr int P2 = 272;               // 256B data + 16B pad
constexpr int WB = 128 * P2;          // 34816 (W: 128 c-rows)
constexpr int HB2 = 64 * P2;          // 17408 (h: 64 n-rows)
constexpr int OFF_HHI = WB;           // 34816
constexpr int OFF_HLO = WB + HB2;     // 52224
constexpr int SMEM_HW = WB + 2 * HB2 + 256;  // 69888

__global__ void __launch_bounds__(256, 2)
gemm_hw_mma(const float* __restrict__ hin, int layer) {
    extern __shared__ __align__(128) char smem[];
    const int tid = threadIdx.x;
    const int wid = tid >> 5, lane = tid & 31;
    const int warpM = wid >> 1, warpN = wid & 1;   // 4M x 2N, warp tile 32x32
    const int batch = blockIdx.y;
    const int n0 = blockIdx.x * 64;
    const uint32_t sb = smem_u32(smem);

    // A: W' hi via cp.async (k-contiguous rows of 256B)
    const char* Wh = (const char*)(g_whi + ((size_t)layer << 14));
    #pragma unroll
    for (int q = 0; q < 8; q++) {
        int id = tid + 256 * q;
        int r = id >> 4, j = id & 15;
        CP16(sb + r * P2 + j * 16, Wh + r * 256 + j * 16);
    }
    CP_COMMIT();

    // B: affine(h) converted + split in-registers -> smem (64 rows x 128 k)
    const float* hb = (hin ? hin : g_h) + ((size_t)batch * NN + n0) * NC;
    #pragma unroll
    for (int q = 0; q < 8; q++) {
        int id = tid + 256 * q;
        int r = id >> 5, g = id & 31;          // r: n-row (0-63), g: float4 within 128 k
        float4 v = *(const float4*)(hb + (size_t)r * NC + g * 4);
        int k0 = g * 4;
        v.x = v.x * g_scale[k0 + 0] + g_shift[k0 + 0];
        v.y = v.y * g_scale[k0 + 1] + g_shift[k0 + 1];
        v.z = v.z * g_scale[k0 + 2] + g_shift[k0 + 2];
        v.w = v.w * g_scale[k0 + 3] + g_shift[k0 + 3];
        __half h0, h1, h2, h3, l0, l1, l2, l3;
        split_f16(v.x, h0, l0);
        split_f16(v.y, h1, l1);
        split_f16(v.z, h2, l2);
        split_f16(v.w, h3, l3);
        __half hh[4] = {h0, h1, h2, h3};
        __half ll[4] = {l0, l1, l2, l3};
        *(uint2*)(smem + OFF_HHI + r * P2 + g * 8) = *(uint2*)hh;
        *(uint2*)(smem + OFF_HLO + r * P2 + g * 8) = *(uint2*)ll;
    }
    CP_WAIT(0);
    __syncthreads();

    float acc[2][4][4] = {};
    const uint32_t a_off = (uint32_t)((warpM * 32 + (lane & 15)) * P2 + ((lane >> 4) << 4));
    const int bg = lane >> 3;
    const uint32_t b_row = (uint32_t)(warpN * 32 + (bg >> 1) * 8 + (lane & 7));
    const uint32_t b_off = b_row * P2 + (uint32_t)((bg & 1) << 4);

    #pragma unroll
    for (int ks = 0; ks < 8; ks++) {
        const uint32_t kb = (uint32_t)(ks * 32);
        uint32_t bh[8], bl[8];
        ldmx4(bh[0], bh[1], bh[2], bh[3], sb + OFF_HHI + b_off + kb);
        ldmx4(bh[4], bh[5], bh[6], bh[7], sb + OFF_HHI + b_off + kb + 16 * P2);
        ldmx4(bl[0], bl[1], bl[2], bl[3], sb + OFF_HLO + b_off + kb);
        ldmx4(bl[4], bl[5], bl[6], bl[7], sb + OFF_HLO + b_off + kb + 16 * P2);
        #pragma unroll
        for (int mi = 0; mi < 2; mi++) {
            uint32_t ah[4];
            uint32_t ao = a_off + (uint32_t)(mi * 16 * P2) + kb;
            ldmx4(ah[0], ah[1], ah[2], ah[3], sb + ao);
            #pragma unroll
            for (int ni = 0; ni < 4; ni++) {
                mma_f16(acc[mi][ni], ah, &bh[ni * 2]);
                mma_f16(acc[mi][ni], ah, &bl[ni * 2]);
            }
        }
    }

    // epilogue: write t as fp16 [b][c][n]
    __half* Tb = g_thi + (size_t)batch * NC * NN;
    #pragma unroll
    for (int mi = 0; mi < 2; mi++) {
        #pragma unroll
        for (int hf = 0; hf < 2; hf++) {
            int c = warpM * 32 + mi * 16 + (lane >> 2) + hf * 8;
            #pragma unroll
            for (int ni = 0; ni < 4; ni++) {
                int n = n0 + warpN * 32 + (lane & 3) * 2 + ni * 8;
                __half2 hv = __floats2half2_rn(acc[mi][ni][hf * 2 + 0],
                                               acc[mi][ni][hf * 2 + 1]);
                *(__half2*)(Tb + (size_t)c * NN + n) = hv;
            }
        }
    }
}

// ---------------- gemm_adj: fp16 mma.sync, 128x128 CTA, 3-stage (R8-proven) ----------------
constexpr int PITCH = 144;
constexpr int ABUF = 128 * PITCH;     // 18432 B
constexpr int STG = 2 * ABUF;         // 36864
constexpr int NSTG = 3;
constexpr int OFF_SUM = NSTG * STG;   // 110592
constexpr int SMEM_SZ = OFF_SUM + 1024;
constexpr int NKT = NN / 64;          // 32 k-tiles

__device__ __forceinline__ void prefetch(uint32_t sbase, int st,
                                         const char* Ab, const char* Hb,
                                         int kt, int tid) {
    uint32_t d = sbase + st * STG;
    const int koff = kt * 128;
    #pragma unroll
    for (int q = 0; q < 4; q++) {
        int id = tid + 256 * q;
        int r = id >> 3, j = id & 7;
        CP16(d + r * PITCH + j * 16, Ab + (size_t)r * (NN * 2) + koff + j * 16);
    }
    #pragma unroll
    for (int q = 0; q < 4; q++) {
        int id = tid + 256 * q;
        int c = id >> 3, j = id & 7;
        CP16(d + ABUF + c * PITCH + j * 16, Hb + (size_t)c * (NN * 2) + koff + j * 16);
    }
    CP_COMMIT();
}

__global__ void __launch_bounds__(256, 2)
gemm_adj_mma(const float* __restrict__ bias, const float* __restrict__ gamma,
             const float* __restrict__ beta) {
    extern __shared__ __align__(128) char smem[];
    const int tid = threadIdx.x;
    const int wid = tid >> 5, lane = tid & 31;
    const int warpM = wid >> 2, warpN = wid & 3;
    const int batch = blockIdx.y;
    const int row0 = blockIdx.x * 128;
    const uint32_t sb = smem_u32(smem);
    float* s_sum = (float*)(smem + OFF_SUM);
    float* s_sq = (float*)(smem + OFF_SUM + 512);
    __shared__ int s_last;

    if (tid < 128) { s_sum[tid] = 0.f; s_sq[tid] = 0.f; }

    const char* Ab = (const char*)(g_adj16 + (size_t)batch * NN * NN + (size_t)row0 * NN);
    const char* Hb = (const char*)(g_thi + (size_t)batch * NC * NN);

    float acc[4][4][4] = {};

    const uint32_t a_off = (uint32_t)((warpM * 64 + (lane & 15)) * PITCH + ((lane >> 4) << 4));
    const int bg = lane >> 3;
    const uint32_t b_row = (uint32_t)(warpN * 32 + (bg >> 1) * 8 + (lane & 7));
    const uint32_t b_off = b_row * PITCH + (uint32_t)((bg & 1) << 4);

    prefetch(sb, 0, Ab, Hb, 0, tid);
    prefetch(sb, 1, Ab, Hb, 1, tid);

    int st = 0;
    for (int kt = 0; kt < NKT; kt++) {
        if (kt < NKT - 1) CP_WAIT(1);
        else CP_WAIT(0);
        __syncthreads();

        if (kt + 2 < NKT)
            prefetch(sb, (st + 2 >= NSTG) ? st + 2 - NSTG : st + 2, Ab, Hb, kt + 2, tid);

        const uint32_t sA = sb + st * STG;
        const uint32_t sB = sA + ABUF;

        #pragma unroll
        for (int ks = 0; ks < 4; ks++) {
            const uint32_t kb = (uint32_t)(ks * 32);
            uint32_t bh[8];
            ldmx4(bh[0], bh[1], bh[2], bh[3], sB + b_off + kb);
            ldmx4(bh[4], bh[5], bh[6], bh[7], sB + b_off + kb + 16 * PITCH);
            #pragma unroll
            for (int mi = 0; mi < 4; mi++) {
                uint32_t a[4];
                ldmx4(a[0], a[1], a[2], a[3], sA + a_off + (uint32_t)(mi * 16 * PITCH) + kb);
                #pragma unroll
                for (int ni = 0; ni < 4; ni++)
                    mma_f16(acc[mi][ni], a, &bh[ni * 2]);
            }
        }
        st = (st + 1 == NSTG) ? 0 : st + 1;
    }

    // epilogue: bias + relu + store + stats
    float2 bv[4];
    const int cbase = warpN * 32 + (lane & 3) * 2;
    #pragma unroll
    for (int ni = 0; ni < 4; ni++)
        bv[ni] = *(const float2*)(bias + cbase + ni * 8);

    float ts[4][2] = {}, tq[4][2] = {};
    float* Yb = g_h + ((size_t)batch * NN + row0) * NC;
    #pragma unroll
    for (int mi = 0; mi < 4; mi++) {
        #pragma unroll
        for (int hf = 0; hf < 2; hf++) {
            int row = warpM * 64 + mi * 16 + (lane >> 2) + hf * 8;
            float* rp = Yb + (size_t)row * NC + cbase;
            #pragma unroll
            for (int ni = 0; ni < 4; ni++) {
                float v0 = fmaxf(acc[mi][ni][hf * 2 + 0] + bv[ni].x, 0.f);
                float v1 = fmaxf(acc[mi][ni][hf * 2 + 1] + bv[ni].y, 0.f);
                *(float2*)(rp + ni * 8) = make_float2(v0, v1);
                ts[ni][0] += v0;
                ts[ni][1] += v1;
                tq[ni][0] = fmaf(v0, v0, tq[ni][0]);
                tq[ni][1] = fmaf(v1, v1, tq[ni][1]);
            }
        }
    }
    #pragma unroll
    for (int ni = 0; ni < 4; ni++) {
        atomicAdd(&s_sum[cbase + ni * 8], ts[ni][0]);
        atomicAdd(&s_sum[cbase + ni * 8 + 1], ts[ni][1]);
        atomicAdd(&s_sq[cbase + ni * 8], tq[ni][0]);
        atomicAdd(&s_sq[cbase + ni * 8 + 1], tq[ni][1]);
    }
    __syncthreads();
    if (tid < 128) {
        atomicAdd(&g_sum[tid], s_sum[tid]);
        atomicAdd(&g_sumsq[tid], s_sq[tid]);
    }

    // fused bn_stats
    __threadfence();
    if (tid == 0)
        s_last = (atomicAdd(&g_cnt, 1) == NB * (NN / 128) - 1) ? 1 : 0;
    __syncthreads();
    if (s_last) {
        if (tid == 0) g_cnt = 0;
        if (tid < NC) {
            const float inv = 1.0f / (float)MTOT;
            float mean = g_sum[tid] * inv;
            float var = g_sumsq[tid] * inv - mean * mean;
            float sc = gamma[tid] * rsqrtf(var + EPS_BN);
            g_scale[tid] = sc;
            g_shift[tid] = beta[tid] - mean * sc;
            g_sum[tid] = 0.f;
            g_sumsq[tid] = 0.f;
        }
    }
}

// ---------------- host ----------------
extern "C" void kernel_launch(void* const* d_in, const int* in_sizes, int n_in,
                              void* d_out, int out_size) {
    const float* x     = (const float*)d_in[0];
    const float* adj   = (const float*)d_in[1];
    const float* W     = (const float*)d_in[2];
    const float* bias  = (const float*)d_in[3];
    const float* gamma = (const float*)d_in[4];
    const float* beta  = (const float*)d_in[5];
    float* out = (float*)d_out;

    // One-time infra (no device memory involved)
    static cudaStream_t s2 = [] {
        cudaStream_t s;
        cudaStreamCreateWithFlags(&s, cudaStreamNonBlocking);
        return s;
    }();
    static cudaEvent_t e0 = [] {
        cudaEvent_t e;
        cudaEventCreateWithFlags(&e, cudaEventDisableTiming);
        return e;
    }();
    static cudaEvent_t e1 = [] {
        cudaEvent_t e;
        cudaEventCreateWithFlags(&e, cudaEventDisableTiming);
        return e;
    }();
    static bool attr_done = [] {
        cudaFuncSetAttribute(gemm_adj_mma, cudaFuncAttributeMaxDynamicSharedMemorySize, SMEM_SZ);
        cudaFuncSetAttribute(gemm_hw_mma, cudaFuncAttributeMaxDynamicSharedMemorySize, SMEM_HW);
        return true;
    }();
    (void)attr_done;

    // fork: prep_adj on side stream, independent of hw(l0)
    cudaEventRecord(e0, 0);
    cudaStreamWaitEvent(s2, e0, 0);
    prep_adj<<<(int)(((size_t)NB * NN * NN / 4) / 256), 256, 0, s2>>>(adj);
    cudaEventRecord(e1, s2);

    prep_w<<<(NL * NC * NC) / 256, 256>>>(W);
    zero_stats_kernel<<<1, NC>>>();
    gemm_hw_mma<<<dim3(NN / 64, NB), 256, SMEM_HW>>>(x, 0);

    cudaStreamWaitEvent(0, e1, 0);   // adj needs g_adj16

    for (int l = 0; l < NL; l++) {
        if (l > 0)
            gemm_hw_mma<<<dim3(NN / 64, NB), 256, SMEM_HW>>>(nullptr, l);
        gemm_adj_mma<<<dim3(NN / 128, NB), 256, SMEM_SZ>>>(bias + (size_t)l * NC,
                                                           gamma + (size_t)l * NC,
                                                           beta + (size_t)l * NC);
    }
    finalize_kernel<<<(MTOT * NC / 4) / 256, 256>>>(out);
}